// round 16
// baseline (speedup 1.0000x reference)
#include <cuda_runtime.h>
#include <cuda_fp16.h>
#include <cstdint>

// Problem: B=4, S=4096, C=O=2048, H=8, DH=256
#define MT    16384
#define KD    2048
#define ND    2048
#define NHEAD 8
#define DHEAD 256
#define LN_EPS 1e-5f

// ---------------- GEMM tiling (fp16 operands, fp32 accum) --------------------
#define BM 128
#define BN 128
#define BK 64                  // 64 halves = 128B per row
#define NKT (KD / BK)          // 32
#define ROWB 144               // row stride bytes (128 + 16 pad) -> ldsm conflict-free
#define A_STAGE_B (BM * ROWB)             // 18432
#define B_STAGE_B (BN * ROWB)             // 18432
#define STAGE_B   (A_STAGE_B + B_STAGE_B) // 36864
#define SMEM_TOTAL (3 * STAGE_B)          // 110592 -> 2 CTAs/SM

// ---------------- scratch ----------------------------------------------------
__device__ __half g_xh[(size_t)MT * KD];      // x rounded to fp16
__device__ __half g_wth[4][(size_t)ND * KD];  // W^T (q,k,v,o), [n][k], fp16
__device__ __half g_atth[(size_t)MT * ND];    // attended, fp16 (O-proj input)
__device__ __half g_qh[(size_t)MT * ND];      // Q fp16
__device__ __half g_kh[(size_t)MT * ND];      // K fp16
__device__ __half g_vh[(size_t)MT * ND];      // V fp16
__device__ float  g_y[(size_t)MT * ND];       // y = attended@Wo + bo + x

// ---------------- helpers ----------------------------------------------------
__device__ __forceinline__ uint32_t smem_u32(const void* p) {
    uint32_t a;
    asm("{ .reg .u64 t; cvta.to.shared.u64 t, %1; cvt.u32.u64 %0, t; }"
        : "=r"(a) : "l"(p));
    return a;
}
__device__ __forceinline__ void cpa16(uint32_t dst, const void* src) {
    asm volatile("cp.async.cg.shared.global [%0], [%1], 16;" :: "r"(dst), "l"(src));
}
__device__ __forceinline__ void ldsm4(uint32_t* r, uint32_t addr) {
    asm volatile("ldmatrix.sync.aligned.m8n8.x4.shared.b16 {%0,%1,%2,%3}, [%4];"
                 : "=r"(r[0]), "=r"(r[1]), "=r"(r[2]), "=r"(r[3]) : "r"(addr));
}
__device__ __forceinline__ void ldsm2(uint32_t* r, uint32_t addr) {
    asm volatile("ldmatrix.sync.aligned.m8n8.x2.shared.b16 {%0,%1}, [%2];"
                 : "=r"(r[0]), "=r"(r[1]) : "r"(addr));
}
__device__ __forceinline__ void mma16(float* c, const uint32_t* a, const uint32_t* b) {
    asm volatile(
        "mma.sync.aligned.m16n8k16.row.col.f32.f16.f16.f32 "
        "{%0,%1,%2,%3},{%4,%5,%6,%7},{%8,%9},{%0,%1,%2,%3};"
        : "+f"(c[0]), "+f"(c[1]), "+f"(c[2]), "+f"(c[3])
        : "r"(a[0]), "r"(a[1]), "r"(a[2]), "r"(a[3]), "r"(b[0]), "r"(b[1]));
}

// ---------------- GEMM core, fp32 output (verified — do not touch) -----------
// out[m][n] = sum_k A[m][k] * Wt[n][k] + bias[n] (+ resid[m][n])
__device__ __forceinline__ void gemm_core(
    const __half* __restrict__ A, const __half* __restrict__ Wt,
    const float* __restrict__ bias, const float* __restrict__ resid,
    float* __restrict__ out, int m0, int n0)
{
    extern __shared__ char smem[];
    const uint32_t sb = smem_u32(smem);
    const int tid  = threadIdx.x;
    const int lane = tid & 31, warp = tid >> 5;
    const int wm   = (warp & 1) * 64;      // 2 warps over M
    const int wn   = (warp >> 1) * 32;     // 4 warps over N
    const int g    = lane >> 2, tg = lane & 3;

    float acc[4][4][4];
#pragma unroll
    for (int i = 0; i < 4; i++)
#pragma unroll
        for (int j = 0; j < 4; j++)
#pragma unroll
            for (int r = 0; r < 4; r++) acc[i][j][r] = 0.f;

    const __half* Ab = A + (size_t)m0 * KD;
    const __half* Wb = Wt + (size_t)n0 * KD;

    auto load_stage = [&](int kt, int s) {
        const uint32_t baseA = sb + s * STAGE_B;
        const uint32_t baseB = baseA + A_STAGE_B;
#pragma unroll
        for (int i = 0; i < 4; i++) {
            const int c  = i * 256 + tid;
            const int r  = c >> 3, cc = c & 7;        // row 0..127, chunk 0..7
            cpa16(baseA + r * ROWB + cc * 16,
                  Ab + (size_t)r * KD + kt * BK + cc * 8);
            cpa16(baseB + r * ROWB + cc * 16,
                  Wb + (size_t)r * KD + kt * BK + cc * 8);
        }
    };

    load_stage(0, 0);
    asm volatile("cp.async.commit_group;" ::: "memory");
    load_stage(1, 1);
    asm volatile("cp.async.commit_group;" ::: "memory");

    const uint32_t offA = (wm + (lane & 15)) * ROWB + (lane >> 4) * 16;
    const uint32_t offB = A_STAGE_B + (wn + (lane & 7)) * ROWB +
                          ((lane >> 3) & 1) * 16;

    int sc = 0, sl = 2;
#pragma unroll 1
    for (int kt = 0; kt < NKT; kt++) {
        asm volatile("cp.async.wait_group 1;" ::: "memory");
        __syncthreads();
        if (kt + 2 < NKT) load_stage(kt + 2, sl);
        asm volatile("cp.async.commit_group;" ::: "memory");

        const uint32_t aA = sb + sc * STAGE_B + offA;
        const uint32_t aB = sb + sc * STAGE_B + offB;
#pragma unroll
        for (int ks = 0; ks < 4; ks++) {          // 4 x k16 = BK 64
            uint32_t af[4][4], bf[4][2];
#pragma unroll
            for (int mi = 0; mi < 4; mi++)
                ldsm4(af[mi], aA + mi * (16 * ROWB) + ks * 32);
#pragma unroll
            for (int ni = 0; ni < 4; ni++)
                ldsm2(bf[ni], aB + ni * (8 * ROWB) + ks * 32);
#pragma unroll
            for (int mi = 0; mi < 4; mi++)
#pragma unroll
                for (int ni = 0; ni < 4; ni++)
                    mma16(acc[mi][ni], af[mi], bf[ni]);
        }
        sc = (sc == 2) ? 0 : sc + 1;
        sl = (sl == 2) ? 0 : sl + 1;
    }

    // epilogue (fp32 stores, optional residual)
#pragma unroll
    for (int mi = 0; mi < 4; mi++) {
        const int m = m0 + wm + mi * 16 + g;
#pragma unroll
        for (int ni = 0; ni < 4; ni++) {
            const int n = n0 + wn + ni * 8 + tg * 2;
            const float b0 = bias[n], b1 = bias[n + 1];
            const size_t o0 = (size_t)m * ND + n;
            const size_t o1 = (size_t)(m + 8) * ND + n;
            float r00 = 0.f, r01 = 0.f, r10 = 0.f, r11 = 0.f;
            if (resid) {
                r00 = resid[o0]; r01 = resid[o0 + 1];
                r10 = resid[o1]; r11 = resid[o1 + 1];
            }
            out[o0]     = acc[mi][ni][0] + b0 + r00;
            out[o0 + 1] = acc[mi][ni][1] + b1 + r01;
            out[o1]     = acc[mi][ni][2] + b0 + r10;
            out[o1 + 1] = acc[mi][ni][3] + b1 + r11;
        }
    }
}

// ---------------- GEMM core, fp16 output (literal copy; epilogue differs) ----
__device__ __forceinline__ void gemm_core_h(
    const __half* __restrict__ A, const __half* __restrict__ Wt,
    const float* __restrict__ bias, __half* __restrict__ out, int m0, int n0)
{
    extern __shared__ char smem[];
    const uint32_t sb = smem_u32(smem);
    const int tid  = threadIdx.x;
    const int lane = tid & 31, warp = tid >> 5;
    const int wm   = (warp & 1) * 64;
    const int wn   = (warp >> 1) * 32;
    const int g    = lane >> 2, tg = lane & 3;

    float acc[4][4][4];
#pragma unroll
    for (int i = 0; i < 4; i++)
#pragma unroll
        for (int j = 0; j < 4; j++)
#pragma unroll
            for (int r = 0; r < 4; r++) acc[i][j][r] = 0.f;

    const __half* Ab = A + (size_t)m0 * KD;
    const __half* Wb = Wt + (size_t)n0 * KD;

    auto load_stage = [&](int kt, int s) {
        const uint32_t baseA = sb + s * STAGE_B;
        const uint32_t baseB = baseA + A_STAGE_B;
#pragma unroll
        for (int i = 0; i < 4; i++) {
            const int c  = i * 256 + tid;
            const int r  = c >> 3, cc = c & 7;
            cpa16(baseA + r * ROWB + cc * 16,
                  Ab + (size_t)r * KD + kt * BK + cc * 8);
            cpa16(baseB + r * ROWB + cc * 16,
                  Wb + (size_t)r * KD + kt * BK + cc * 8);
        }
    };

    load_stage(0, 0);
    asm volatile("cp.async.commit_group;" ::: "memory");
    load_stage(1, 1);
    asm volatile("cp.async.commit_group;" ::: "memory");

    const uint32_t offA = (wm + (lane & 15)) * ROWB + (lane >> 4) * 16;
    const uint32_t offB = A_STAGE_B + (wn + (lane & 7)) * ROWB +
                          ((lane >> 3) & 1) * 16;

    int sc = 0, sl = 2;
#pragma unroll 1
    for (int kt = 0; kt < NKT; kt++) {
        asm volatile("cp.async.wait_group 1;" ::: "memory");
        __syncthreads();
        if (kt + 2 < NKT) load_stage(kt + 2, sl);
        asm volatile("cp.async.commit_group;" ::: "memory");

        const uint32_t aA = sb + sc * STAGE_B + offA;
        const uint32_t aB = sb + sc * STAGE_B + offB;
#pragma unroll
        for (int ks = 0; ks < 4; ks++) {
            uint32_t af[4][4], bf[4][2];
#pragma unroll
            for (int mi = 0; mi < 4; mi++)
                ldsm4(af[mi], aA + mi * (16 * ROWB) + ks * 32);
#pragma unroll
            for (int ni = 0; ni < 4; ni++)
                ldsm2(bf[ni], aB + ni * (8 * ROWB) + ks * 32);
#pragma unroll
            for (int mi = 0; mi < 4; mi++)
#pragma unroll
                for (int ni = 0; ni < 4; ni++)
                    mma16(acc[mi][ni], af[mi], bf[ni]);
        }
        sc = (sc == 2) ? 0 : sc + 1;
        sl = (sl == 2) ? 0 : sl + 1;
    }

    // epilogue (half2 stores, no residual)
#pragma unroll
    for (int mi = 0; mi < 4; mi++) {
        const int m = m0 + wm + mi * 16 + g;
#pragma unroll
        for (int ni = 0; ni < 4; ni++) {
            const int n = n0 + wn + ni * 8 + tg * 2;
            const float b0 = bias[n], b1 = bias[n + 1];
            const size_t o0 = (size_t)m * ND + n;
            const size_t o1 = (size_t)(m + 8) * ND + n;
            *(__half2*)(out + o0) =
                __floats2half2_rn(acc[mi][ni][0] + b0, acc[mi][ni][1] + b1);
            *(__half2*)(out + o1) =
                __floats2half2_rn(acc[mi][ni][2] + b0, acc[mi][ni][3] + b1);
        }
    }
}

__global__ void __launch_bounds__(256, 2) gemm_qkv_kernel(
    const float* __restrict__ bq, const float* __restrict__ bk,
    const float* __restrict__ bv)
{
    const int z  = blockIdx.x >> 4;          // bn fastest -> weights L2-resident
    const int bn = blockIdx.x & 15;
    const float* bias = (z == 0) ? bq : ((z == 1) ? bk : bv);
    __half* out       = (z == 0) ? g_qh : ((z == 1) ? g_kh : g_vh);
    gemm_core_h(g_xh, g_wth[z], bias, out, blockIdx.y * BM, bn * BN);
}

__global__ void __launch_bounds__(256, 2) gemm_o_kernel(
    const float* __restrict__ bo, const float* __restrict__ x)
{
    gemm_core(g_atth, g_wth[3], bo, x, g_y, blockIdx.y * BM, blockIdx.x * BN);
}

// ---------------- prep: x -> fp16; W -> W^T fp16 -----------------------------
__global__ void __launch_bounds__(256) prep_x_kernel(const float* __restrict__ x)
{
    const size_t i = ((size_t)blockIdx.x * 256 + threadIdx.x) * 8;
    const float4 v0 = *(const float4*)(x + i);
    const float4 v1 = *(const float4*)(x + i + 4);
    __half2 h[4];
    h[0] = __floats2half2_rn(v0.x, v0.y);
    h[1] = __floats2half2_rn(v0.z, v0.w);
    h[2] = __floats2half2_rn(v1.x, v1.y);
    h[3] = __floats2half2_rn(v1.z, v1.w);
    *(uint4*)(g_xh + i) = *(uint4*)h;
}

__global__ void __launch_bounds__(256) prep_w_kernel(
    const float* __restrict__ Wq, const float* __restrict__ Wk,
    const float* __restrict__ Wv, const float* __restrict__ Wo)
{
    __shared__ float t[32][33];
    const int z = blockIdx.z;
    const float* W = (z == 0) ? Wq : ((z == 1) ? Wk : ((z == 2) ? Wv : Wo));
    const int k0 = blockIdx.y * 32, n0 = blockIdx.x * 32;
    const int tx = threadIdx.x & 31, ty = threadIdx.x >> 5;
#pragma unroll
    for (int i = 0; i < 4; i++)
        t[ty + i * 8][tx] = W[(size_t)(k0 + ty + i * 8) * ND + n0 + tx];
    __syncthreads();
    __half* o = g_wth[z];
#pragma unroll
    for (int i = 0; i < 4; i++) {
        const int r = ty + i * 8;                  // n offset
        o[(size_t)(n0 + r) * KD + k0 + tx] = __float2half_rn(t[tx][r]);
    }
}

// ---------------- per-position 8x8 head attention ----------------------------
// 256 threads: warp h owns head h; lane owns d-pairs (lane+32j), j=0..3.
// K,V converted once into float2 smem; q in regs. Score loop j-outer with
// batched K loads (8 independent LDS.64 in flight); per-t accumulation order
// identical to the verified round-14 version. Reg cap raised to 64 for ILP.
__global__ void __launch_bounds__(256, 4) attn_kernel()
{
    __shared__ float2 sk2[ND / 2];       // 8 KB
    __shared__ float2 sv2[ND / 2];       // 8 KB
    const int p = blockIdx.x, tid = threadIdx.x;
    const int h = tid >> 5, lane = tid & 31;

    // stage K and V: half2 gmem loads, convert once, conflict-free STS.64
    {
        const __half2* kh = (const __half2*)(g_kh + (size_t)p * ND);
        const __half2* vh = (const __half2*)(g_vh + (size_t)p * ND);
#pragma unroll
        for (int j = 0; j < 4; j++) {
            const int idx = tid + 256 * j;
            sk2[idx] = __half22float2(kh[idx]);
            sv2[idx] = __half22float2(vh[idx]);
        }
    }
    // q pairs for this warp's head (coalesced gmem, convert to float regs)
    float2 q2[4];
    {
        const __half2* qg = (const __half2*)(g_qh + (size_t)p * ND + h * DHEAD);
#pragma unroll
        for (int j = 0; j < 4; j++)
            q2[j] = __half22float2(qg[lane + 32 * j]);
    }
    __syncthreads();

    // scores: j outer, batched loads of all 8 heads' K pairs
    float s[NHEAD];
#pragma unroll
    for (int t = 0; t < NHEAD; t++) s[t] = 0.f;
#pragma unroll
    for (int j = 0; j < 4; j++) {
        const int idx = lane + 32 * j;
        float2 kk[NHEAD];
#pragma unroll
        for (int t = 0; t < NHEAD; t++)
            kk[t] = sk2[t * (DHEAD / 2) + idx];
#pragma unroll
        for (int t = 0; t < NHEAD; t++)
            s[t] += q2[j].x * kk[t].x + q2[j].y * kk[t].y;
    }
#pragma unroll
    for (int t = 0; t < NHEAD; t++) {
#pragma unroll
        for (int off = 16; off > 0; off >>= 1)
            s[t] += __shfl_xor_sync(0xffffffffu, s[t], off);
        s[t] *= 0.0625f;           // 1/sqrt(256)
    }
    float mx = s[0];
#pragma unroll
    for (int t = 1; t < NHEAD; t++) mx = fmaxf(mx, s[t]);
    float sum = 0.f;
#pragma unroll
    for (int t = 0; t < NHEAD; t++) { s[t] = __expf(s[t] - mx); sum += s[t]; }
    const float inv = 1.f / sum;

    // attended: j outer, batched loads of all 8 heads' V pairs
    __half2* ao = (__half2*)(g_atth + (size_t)p * ND + h * DHEAD);
#pragma unroll
    for (int j = 0; j < 4; j++) {
        const int idx = lane + 32 * j;
        float2 vv[NHEAD];
#pragma unroll
        for (int t = 0; t < NHEAD; t++)
            vv[t] = sv2[t * (DHEAD / 2) + idx];
        float ox = 0.f, oy = 0.f;
#pragma unroll
        for (int t = 0; t < NHEAD; t++) {
            ox += s[t] * vv[t].x;
            oy += s[t] * vv[t].y;
        }
        ao[idx] = __floats2half2_rn(ox * inv, oy * inv);
    }
}

// ---------------- LayerNorm --------------------------------------------------
__global__ void __launch_bounds__(256) ln_kernel(
    const float* __restrict__ gamma, const float* __restrict__ beta,
    float* __restrict__ out)
{
    const int row = blockIdx.x, tid = threadIdx.x;
    const float4* y4 = (const float4*)(g_y + (size_t)row * KD);
    const float4 v0 = y4[tid];
    const float4 v1 = y4[tid + 256];
    float s = v0.x + v0.y + v0.z + v0.w + v1.x + v1.y + v1.z + v1.w;
    float q = v0.x * v0.x + v0.y * v0.y + v0.z * v0.z + v0.w * v0.w +
              v1.x * v1.x + v1.y * v1.y + v1.z * v1.z + v1.w * v1.w;
#pragma unroll
    for (int off = 16; off > 0; off >>= 1) {
        s += __shfl_xor_sync(0xffffffffu, s, off);
        q += __shfl_xor_sync(0xffffffffu, q, off);
    }
    __shared__ float rs[8], rq[8];
    const int warp = tid >> 5, lane = tid & 31;
    if (lane == 0) { rs[warp] = s; rq[warp] = q; }
    __syncthreads();
    float S = 0.f, Q = 0.f;
#pragma unroll
    for (int i = 0; i < 8; i++) { S += rs[i]; Q += rq[i]; }
    const float mu   = S * (1.f / KD);
    const float var  = Q * (1.f / KD) - mu * mu;
    const float rstd = rsqrtf(var + LN_EPS);

    const float4* g4 = (const float4*)gamma;
    const float4* b4 = (const float4*)beta;
    float4* o4 = (float4*)(out + (size_t)row * KD);

    float4 ga = g4[tid], be = b4[tid], o;
    o.x = ga.x * (v0.x - mu) * rstd + be.x;
    o.y = ga.y * (v0.y - mu) * rstd + be.y;
    o.z = ga.z * (v0.z - mu) * rstd + be.z;
    o.w = ga.w * (v0.w - mu) * rstd + be.w;
    o4[tid] = o;
    ga = g4[tid + 256]; be = b4[tid + 256];
    o.x = ga.x * (v1.x - mu) * rstd + be.x;
    o.y = ga.y * (v1.y - mu) * rstd + be.y;
    o.z = ga.z * (v1.z - mu) * rstd + be.z;
    o.w = ga.w * (v1.w - mu) * rstd + be.w;
    o4[tid + 256] = o;
}

// ---------------- launch -----------------------------------------------------
extern "C" void kernel_launch(void* const* d_in, const int* in_sizes, int n_in,
                              void* d_out, int out_size)
{
    const float* x     = (const float*)d_in[0];
    const float* Wq    = (const float*)d_in[1];
    const float* bq    = (const float*)d_in[2];
    const float* Wk    = (const float*)d_in[3];
    const float* bk    = (const float*)d_in[4];
    const float* Wv    = (const float*)d_in[5];
    const float* bv    = (const float*)d_in[6];
    const float* Wo    = (const float*)d_in[7];
    const float* bo    = (const float*)d_in[8];
    const float* gamma = (const float*)d_in[9];
    const float* beta  = (const float*)d_in[10];
    float* out = (float*)d_out;

    cudaFuncSetAttribute(gemm_qkv_kernel,
                         cudaFuncAttributeMaxDynamicSharedMemorySize, SMEM_TOTAL);
    cudaFuncSetAttribute(gemm_o_kernel,
                         cudaFuncAttributeMaxDynamicSharedMemorySize, SMEM_TOTAL);

    prep_x_kernel<<<(MT * (size_t)KD) / 2048, 256>>>(x);
    prep_w_kernel<<<dim3(ND / 32, KD / 32, 4), 256>>>(Wq, Wk, Wv, Wo);
    gemm_qkv_kernel<<<dim3(48, MT / BM), 256, SMEM_TOTAL>>>(bq, bk, bv);
    attn_kernel<<<MT, 256>>>();
    gemm_o_kernel<<<dim3(ND / BN, MT / BM), 256, SMEM_TOTAL>>>(bo, x);
    ln_kernel<<<MT, 256>>>(gamma, beta, out);
}

// round 17
// speedup vs baseline: 1.5385x; 1.5385x over previous
#include <cuda_runtime.h>
#include <cuda_fp16.h>
#include <cstdint>

// Problem: B=4, S=4096, C=O=2048, H=8, DH=256
#define MT    16384
#define KD    2048
#define ND    2048
#define NHEAD 8
#define DHEAD 256
#define LN_EPS 1e-5f

// ---------------- GEMM tiling (fp16 operands, fp32 accum) --------------------
#define BM 128
#define BN 128
#define BK 64                  // 64 halves = 128B per row
#define NKT (KD / BK)          // 32
#define ROWB 144               // row stride bytes (128 + 16 pad) -> ldsm conflict-free
#define A_STAGE_B (BM * ROWB)             // 18432
#define B_STAGE_B (BN * ROWB)             // 18432
#define STAGE_B   (A_STAGE_B + B_STAGE_B) // 36864
#define SMEM_TOTAL (3 * STAGE_B)          // 110592 -> 2 CTAs/SM

// ---------------- scratch ----------------------------------------------------
__device__ __half g_xh[(size_t)MT * KD];      // x rounded to fp16
__device__ __half g_wth[4][(size_t)ND * KD];  // W^T (q,k,v,o), [n][k], fp16
__device__ __half g_atth[(size_t)MT * ND];    // attended, fp16 (O-proj input)
__device__ __half g_qh[(size_t)MT * ND];      // Q fp16
__device__ __half g_kh[(size_t)MT * ND];      // K fp16
__device__ __half g_vh[(size_t)MT * ND];      // V fp16
__device__ float  g_y[(size_t)MT * ND];       // y = attended@Wo + bo + x

// ---------------- helpers ----------------------------------------------------
__device__ __forceinline__ uint32_t smem_u32(const void* p) {
    uint32_t a;
    asm("{ .reg .u64 t; cvta.to.shared.u64 t, %1; cvt.u32.u64 %0, t; }"
        : "=r"(a) : "l"(p));
    return a;
}
__device__ __forceinline__ void cpa16(uint32_t dst, const void* src) {
    asm volatile("cp.async.cg.shared.global [%0], [%1], 16;" :: "r"(dst), "l"(src));
}
__device__ __forceinline__ void ldsm4(uint32_t* r, uint32_t addr) {
    asm volatile("ldmatrix.sync.aligned.m8n8.x4.shared.b16 {%0,%1,%2,%3}, [%4];"
                 : "=r"(r[0]), "=r"(r[1]), "=r"(r[2]), "=r"(r[3]) : "r"(addr));
}
__device__ __forceinline__ void ldsm2(uint32_t* r, uint32_t addr) {
    asm volatile("ldmatrix.sync.aligned.m8n8.x2.shared.b16 {%0,%1}, [%2];"
                 : "=r"(r[0]), "=r"(r[1]) : "r"(addr));
}
__device__ __forceinline__ void mma16(float* c, const uint32_t* a, const uint32_t* b) {
    asm volatile(
        "mma.sync.aligned.m16n8k16.row.col.f32.f16.f16.f32 "
        "{%0,%1,%2,%3},{%4,%5,%6,%7},{%8,%9},{%0,%1,%2,%3};"
        : "+f"(c[0]), "+f"(c[1]), "+f"(c[2]), "+f"(c[3])
        : "r"(a[0]), "r"(a[1]), "r"(a[2]), "r"(a[3]), "r"(b[0]), "r"(b[1]));
}

// ---------------- GEMM core, fp32 output (verified — do not touch) -----------
// out[m][n] = sum_k A[m][k] * Wt[n][k] + bias[n] (+ resid[m][n])
__device__ __forceinline__ void gemm_core(
    const __half* __restrict__ A, const __half* __restrict__ Wt,
    const float* __restrict__ bias, const float* __restrict__ resid,
    float* __restrict__ out, int m0, int n0)
{
    extern __shared__ char smem[];
    const uint32_t sb = smem_u32(smem);
    const int tid  = threadIdx.x;
    const int lane = tid & 31, warp = tid >> 5;
    const int wm   = (warp & 1) * 64;      // 2 warps over M
    const int wn   = (warp >> 1) * 32;     // 4 warps over N
    const int g    = lane >> 2, tg = lane & 3;

    float acc[4][4][4];
#pragma unroll
    for (int i = 0; i < 4; i++)
#pragma unroll
        for (int j = 0; j < 4; j++)
#pragma unroll
            for (int r = 0; r < 4; r++) acc[i][j][r] = 0.f;

    const __half* Ab = A + (size_t)m0 * KD;
    const __half* Wb = Wt + (size_t)n0 * KD;

    auto load_stage = [&](int kt, int s) {
        const uint32_t baseA = sb + s * STAGE_B;
        const uint32_t baseB = baseA + A_STAGE_B;
#pragma unroll
        for (int i = 0; i < 4; i++) {
            const int c  = i * 256 + tid;
            const int r  = c >> 3, cc = c & 7;        // row 0..127, chunk 0..7
            cpa16(baseA + r * ROWB + cc * 16,
                  Ab + (size_t)r * KD + kt * BK + cc * 8);
            cpa16(baseB + r * ROWB + cc * 16,
                  Wb + (size_t)r * KD + kt * BK + cc * 8);
        }
    };

    load_stage(0, 0);
    asm volatile("cp.async.commit_group;" ::: "memory");
    load_stage(1, 1);
    asm volatile("cp.async.commit_group;" ::: "memory");

    const uint32_t offA = (wm + (lane & 15)) * ROWB + (lane >> 4) * 16;
    const uint32_t offB = A_STAGE_B + (wn + (lane & 7)) * ROWB +
                          ((lane >> 3) & 1) * 16;

    int sc = 0, sl = 2;
#pragma unroll 1
    for (int kt = 0; kt < NKT; kt++) {
        asm volatile("cp.async.wait_group 1;" ::: "memory");
        __syncthreads();
        if (kt + 2 < NKT) load_stage(kt + 2, sl);
        asm volatile("cp.async.commit_group;" ::: "memory");

        const uint32_t aA = sb + sc * STAGE_B + offA;
        const uint32_t aB = sb + sc * STAGE_B + offB;
#pragma unroll
        for (int ks = 0; ks < 4; ks++) {          // 4 x k16 = BK 64
            uint32_t af[4][4], bf[4][2];
#pragma unroll
            for (int mi = 0; mi < 4; mi++)
                ldsm4(af[mi], aA + mi * (16 * ROWB) + ks * 32);
#pragma unroll
            for (int ni = 0; ni < 4; ni++)
                ldsm2(bf[ni], aB + ni * (8 * ROWB) + ks * 32);
#pragma unroll
            for (int mi = 0; mi < 4; mi++)
#pragma unroll
                for (int ni = 0; ni < 4; ni++)
                    mma16(acc[mi][ni], af[mi], bf[ni]);
        }
        sc = (sc == 2) ? 0 : sc + 1;
        sl = (sl == 2) ? 0 : sl + 1;
    }

    // epilogue (fp32 stores, optional residual)
#pragma unroll
    for (int mi = 0; mi < 4; mi++) {
        const int m = m0 + wm + mi * 16 + g;
#pragma unroll
        for (int ni = 0; ni < 4; ni++) {
            const int n = n0 + wn + ni * 8 + tg * 2;
            const float b0 = bias[n], b1 = bias[n + 1];
            const size_t o0 = (size_t)m * ND + n;
            const size_t o1 = (size_t)(m + 8) * ND + n;
            float r00 = 0.f, r01 = 0.f, r10 = 0.f, r11 = 0.f;
            if (resid) {
                r00 = resid[o0]; r01 = resid[o0 + 1];
                r10 = resid[o1]; r11 = resid[o1 + 1];
            }
            out[o0]     = acc[mi][ni][0] + b0 + r00;
            out[o0 + 1] = acc[mi][ni][1] + b1 + r01;
            out[o1]     = acc[mi][ni][2] + b0 + r10;
            out[o1 + 1] = acc[mi][ni][3] + b1 + r11;
        }
    }
}

// ---------------- GEMM core, fp16 output (literal copy; epilogue differs) ----
__device__ __forceinline__ void gemm_core_h(
    const __half* __restrict__ A, const __half* __restrict__ Wt,
    const float* __restrict__ bias, __half* __restrict__ out, int m0, int n0)
{
    extern __shared__ char smem[];
    const uint32_t sb = smem_u32(smem);
    const int tid  = threadIdx.x;
    const int lane = tid & 31, warp = tid >> 5;
    const int wm   = (warp & 1) * 64;
    const int wn   = (warp >> 1) * 32;
    const int g    = lane >> 2, tg = lane & 3;

    float acc[4][4][4];
#pragma unroll
    for (int i = 0; i < 4; i++)
#pragma unroll
        for (int j = 0; j < 4; j++)
#pragma unroll
            for (int r = 0; r < 4; r++) acc[i][j][r] = 0.f;

    const __half* Ab = A + (size_t)m0 * KD;
    const __half* Wb = Wt + (size_t)n0 * KD;

    auto load_stage = [&](int kt, int s) {
        const uint32_t baseA = sb + s * STAGE_B;
        const uint32_t baseB = baseA + A_STAGE_B;
#pragma unroll
        for (int i = 0; i < 4; i++) {
            const int c  = i * 256 + tid;
            const int r  = c >> 3, cc = c & 7;
            cpa16(baseA + r * ROWB + cc * 16,
                  Ab + (size_t)r * KD + kt * BK + cc * 8);
            cpa16(baseB + r * ROWB + cc * 16,
                  Wb + (size_t)r * KD + kt * BK + cc * 8);
        }
    };

    load_stage(0, 0);
    asm volatile("cp.async.commit_group;" ::: "memory");
    load_stage(1, 1);
    asm volatile("cp.async.commit_group;" ::: "memory");

    const uint32_t offA = (wm + (lane & 15)) * ROWB + (lane >> 4) * 16;
    const uint32_t offB = A_STAGE_B + (wn + (lane & 7)) * ROWB +
                          ((lane >> 3) & 1) * 16;

    int sc = 0, sl = 2;
#pragma unroll 1
    for (int kt = 0; kt < NKT; kt++) {
        asm volatile("cp.async.wait_group 1;" ::: "memory");
        __syncthreads();
        if (kt + 2 < NKT) load_stage(kt + 2, sl);
        asm volatile("cp.async.commit_group;" ::: "memory");

        const uint32_t aA = sb + sc * STAGE_B + offA;
        const uint32_t aB = sb + sc * STAGE_B + offB;
#pragma unroll
        for (int ks = 0; ks < 4; ks++) {
            uint32_t af[4][4], bf[4][2];
#pragma unroll
            for (int mi = 0; mi < 4; mi++)
                ldsm4(af[mi], aA + mi * (16 * ROWB) + ks * 32);
#pragma unroll
            for (int ni = 0; ni < 4; ni++)
                ldsm2(bf[ni], aB + ni * (8 * ROWB) + ks * 32);
#pragma unroll
            for (int mi = 0; mi < 4; mi++)
#pragma unroll
                for (int ni = 0; ni < 4; ni++)
                    mma16(acc[mi][ni], af[mi], bf[ni]);
        }
        sc = (sc == 2) ? 0 : sc + 1;
        sl = (sl == 2) ? 0 : sl + 1;
    }

    // epilogue (half2 stores, no residual)
#pragma unroll
    for (int mi = 0; mi < 4; mi++) {
        const int m = m0 + wm + mi * 16 + g;
#pragma unroll
        for (int ni = 0; ni < 4; ni++) {
            const int n = n0 + wn + ni * 8 + tg * 2;
            const float b0 = bias[n], b1 = bias[n + 1];
            const size_t o0 = (size_t)m * ND + n;
            const size_t o1 = (size_t)(m + 8) * ND + n;
            *(__half2*)(out + o0) =
                __floats2half2_rn(acc[mi][ni][0] + b0, acc[mi][ni][1] + b1);
            *(__half2*)(out + o1) =
                __floats2half2_rn(acc[mi][ni][2] + b0, acc[mi][ni][3] + b1);
        }
    }
}

__global__ void __launch_bounds__(256, 2) gemm_qkv_kernel(
    const float* __restrict__ bq, const float* __restrict__ bk,
    const float* __restrict__ bv)
{
    const int z  = blockIdx.x >> 4;          // bn fastest -> weights L2-resident
    const int bn = blockIdx.x & 15;
    const float* bias = (z == 0) ? bq : ((z == 1) ? bk : bv);
    __half* out       = (z == 0) ? g_qh : ((z == 1) ? g_kh : g_vh);
    gemm_core_h(g_xh, g_wth[z], bias, out, blockIdx.y * BM, bn * BN);
}

__global__ void __launch_bounds__(256, 2) gemm_o_kernel(
    const float* __restrict__ bo, const float* __restrict__ x)
{
    gemm_core(g_atth, g_wth[3], bo, x, g_y, blockIdx.y * BM, blockIdx.x * BN);
}

// ---------------- fused prep: W -> W^T fp16 (z<4) and x -> fp16 (z==4) -------
__global__ void __launch_bounds__(256) prep_kernel(
    const float* __restrict__ x,
    const float* __restrict__ Wq, const float* __restrict__ Wk,
    const float* __restrict__ Wv, const float* __restrict__ Wo)
{
    const int z = blockIdx.z;
    if (z == 4) {
        // x -> fp16: 4096 blocks in (x,y), grid-stride chunks of 8 floats
        const size_t blk = (size_t)blockIdx.y * 64 + blockIdx.x;   // 0..4095
        const size_t stride = (size_t)4096 * 256 * 8;
#pragma unroll
        for (int i = 0; i < 4; i++) {
            const size_t idx = (blk * 256 + threadIdx.x) * 8 + i * stride;
            const float4 v0 = *(const float4*)(x + idx);
            const float4 v1 = *(const float4*)(x + idx + 4);
            __half2 h[4];
            h[0] = __floats2half2_rn(v0.x, v0.y);
            h[1] = __floats2half2_rn(v0.z, v0.w);
            h[2] = __floats2half2_rn(v1.x, v1.y);
            h[3] = __floats2half2_rn(v1.z, v1.w);
            *(uint4*)(g_xh + idx) = *(uint4*)h;
        }
        return;
    }
    __shared__ float t[32][33];
    const float* W = (z == 0) ? Wq : ((z == 1) ? Wk : ((z == 2) ? Wv : Wo));
    const int k0 = blockIdx.y * 32, n0 = blockIdx.x * 32;
    const int tx = threadIdx.x & 31, ty = threadIdx.x >> 5;
#pragma unroll
    for (int i = 0; i < 4; i++)
        t[ty + i * 8][tx] = W[(size_t)(k0 + ty + i * 8) * ND + n0 + tx];
    __syncthreads();
    __half* o = g_wth[z];
#pragma unroll
    for (int i = 0; i < 4; i++) {
        const int r = ty + i * 8;                  // n offset
        o[(size_t)(n0 + r) * KD + k0 + tx] = __float2half_rn(t[tx][r]);
    }
}

// ---------------- per-position 8x8 head attention (verified, 96us) -----------
// 256 threads: warp h owns head h; lane owns d-pairs (lane+32j), j=0..3.
// K,V read as half2 from gmem, converted ONCE into float2 smem at staging;
// q converted to float regs. Output fp16 for the O-proj GEMM.
__global__ void __launch_bounds__(256) attn_kernel()
{
    __shared__ float2 sk2[ND / 2];       // 8 KB
    __shared__ float2 sv2[ND / 2];       // 8 KB
    const int p = blockIdx.x, tid = threadIdx.x;
    const int h = tid >> 5, lane = tid & 31;

    // stage K and V: half2 gmem loads, convert once, conflict-free STS.64
    {
        const __half2* kh = (const __half2*)(g_kh + (size_t)p * ND);
        const __half2* vh = (const __half2*)(g_vh + (size_t)p * ND);
#pragma unroll
        for (int j = 0; j < 4; j++) {
            const int idx = tid + 256 * j;
            sk2[idx] = __half22float2(kh[idx]);
            sv2[idx] = __half22float2(vh[idx]);
        }
    }
    // q pairs for this warp's head (coalesced gmem, convert to float regs)
    float2 q2[4];
    {
        const __half2* qg = (const __half2*)(g_qh + (size_t)p * ND + h * DHEAD);
#pragma unroll
        for (int j = 0; j < 4; j++)
            q2[j] = __half22float2(qg[lane + 32 * j]);
    }
    __syncthreads();

    float s[NHEAD];
#pragma unroll
    for (int t = 0; t < NHEAD; t++) {
        const float2* kt = sk2 + t * (DHEAD / 2);
        float part = 0.f;
#pragma unroll
        for (int j = 0; j < 4; j++) {
            const float2 k2 = kt[lane + 32 * j];
            part += q2[j].x * k2.x + q2[j].y * k2.y;
        }
#pragma unroll
        for (int off = 16; off > 0; off >>= 1)
            part += __shfl_xor_sync(0xffffffffu, part, off);
        s[t] = part * 0.0625f;     // 1/sqrt(256)
    }
    float mx = s[0];
#pragma unroll
    for (int t = 1; t < NHEAD; t++) mx = fmaxf(mx, s[t]);
    float sum = 0.f;
#pragma unroll
    for (int t = 0; t < NHEAD; t++) { s[t] = __expf(s[t] - mx); sum += s[t]; }
    const float inv = 1.f / sum;

    __half2* ao = (__half2*)(g_atth + (size_t)p * ND + h * DHEAD);
#pragma unroll
    for (int j = 0; j < 4; j++) {
        float ox = 0.f, oy = 0.f;
#pragma unroll
        for (int t = 0; t < NHEAD; t++) {
            const float2 v2 = sv2[t * (DHEAD / 2) + lane + 32 * j];
            ox += s[t] * v2.x;
            oy += s[t] * v2.y;
        }
        ao[lane + 32 * j] = __floats2half2_rn(ox * inv, oy * inv);
    }
}

// ---------------- LayerNorm --------------------------------------------------
__global__ void __launch_bounds__(256) ln_kernel(
    const float* __restrict__ gamma, const float* __restrict__ beta,
    float* __restrict__ out)
{
    const int row = blockIdx.x, tid = threadIdx.x;
    const float4* y4 = (const float4*)(g_y + (size_t)row * KD);
    const float4 v0 = y4[tid];
    const float4 v1 = y4[tid + 256];
    float s = v0.x + v0.y + v0.z + v0.w + v1.x + v1.y + v1.z + v1.w;
    float q = v0.x * v0.x + v0.y * v0.y + v0.z * v0.z + v0.w * v0.w +
              v1.x * v1.x + v1.y * v1.y + v1.z * v1.z + v1.w * v1.w;
#pragma unroll
    for (int off = 16; off > 0; off >>= 1) {
        s += __shfl_xor_sync(0xffffffffu, s, off);
        q += __shfl_xor_sync(0xffffffffu, q, off);
    }
    __shared__ float rs[8], rq[8];
    const int warp = tid >> 5, lane = tid & 31;
    if (lane == 0) { rs[warp] = s; rq[warp] = q; }
    __syncthreads();
    float S = 0.f, Q = 0.f;
#pragma unroll
    for (int i = 0; i < 8; i++) { S += rs[i]; Q += rq[i]; }
    const float mu   = S * (1.f / KD);
    const float var  = Q * (1.f / KD) - mu * mu;
    const float rstd = rsqrtf(var + LN_EPS);

    const float4* g4 = (const float4*)gamma;
    const float4* b4 = (const float4*)beta;
    float4* o4 = (float4*)(out + (size_t)row * KD);

    float4 ga = g4[tid], be = b4[tid], o;
    o.x = ga.x * (v0.x - mu) * rstd + be.x;
    o.y = ga.y * (v0.y - mu) * rstd + be.y;
    o.z = ga.z * (v0.z - mu) * rstd + be.z;
    o.w = ga.w * (v0.w - mu) * rstd + be.w;
    o4[tid] = o;
    ga = g4[tid + 256]; be = b4[tid + 256];
    o.x = ga.x * (v1.x - mu) * rstd + be.x;
    o.y = ga.y * (v1.y - mu) * rstd + be.y;
    o.z = ga.z * (v1.z - mu) * rstd + be.z;
    o.w = ga.w * (v1.w - mu) * rstd + be.w;
    o4[tid + 256] = o;
}

// ---------------- launch -----------------------------------------------------
extern "C" void kernel_launch(void* const* d_in, const int* in_sizes, int n_in,
                              void* d_out, int out_size)
{
    const float* x     = (const float*)d_in[0];
    const float* Wq    = (const float*)d_in[1];
    const float* bq    = (const float*)d_in[2];
    const float* Wk    = (const float*)d_in[3];
    const float* bk    = (const float*)d_in[4];
    const float* Wv    = (const float*)d_in[5];
    const float* bv    = (const float*)d_in[6];
    const float* Wo    = (const float*)d_in[7];
    const float* bo    = (const float*)d_in[8];
    const float* gamma = (const float*)d_in[9];
    const float* beta  = (const float*)d_in[10];
    float* out = (float*)d_out;

    cudaFuncSetAttribute(gemm_qkv_kernel,
                         cudaFuncAttributeMaxDynamicSharedMemorySize, SMEM_TOTAL);
    cudaFuncSetAttribute(gemm_o_kernel,
                         cudaFuncAttributeMaxDynamicSharedMemorySize, SMEM_TOTAL);

    prep_kernel<<<dim3(64, 64, 5), 256>>>(x, Wq, Wk, Wv, Wo);
    gemm_qkv_kernel<<<dim3(48, MT / BM), 256, SMEM_TOTAL>>>(bq, bk, bv);
    attn_kernel<<<MT, 256>>>();
    gemm_o_kernel<<<dim3(ND / BN, MT / BM), 256, SMEM_TOTAL>>>(bo, x);
    ln_kernel<<<MT, 256>>>(gamma, beta, out);
}